// round 2
// baseline (speedup 1.0000x reference)
#include <cuda_runtime.h>
#include <cuda_bf16.h>

#define S_LEN 6
#define E_DIM 256
#define NH    8
#define HD    32
#define HW    4096   // 64*64
#define B_MAX 16

// Scratch (no cudaMalloc allowed): g = pooled+pos features, og = attention output proj
__device__ float g_buf[B_MAX * S_LEN * E_DIM];
__device__ float og_buf[B_MAX * S_LEN * E_DIM];

// -------------------------------------------------------------------------
// Kernel 1: global spatial mean over 64x64 + temporal_pos  -> g[b,s,e]
// One block per (b,s,e); 256 threads reduce 4096 contiguous floats.
// -------------------------------------------------------------------------
__global__ void __launch_bounds__(256) pool_kernel(
    const float* __restrict__ ff, const float* __restrict__ tpos, int total)
{
    int idx = blockIdx.x;                 // b*S*E + s*E + e
    if (idx >= total) return;
    const float4* p = reinterpret_cast<const float4*>(ff + (size_t)idx * HW);

    float sum = 0.f;
#pragma unroll
    for (int i = 0; i < 4; i++) {
        float4 v = p[threadIdx.x + i * 256];
        sum += (v.x + v.y) + (v.z + v.w);
    }
    // warp reduce
#pragma unroll
    for (int off = 16; off > 0; off >>= 1)
        sum += __shfl_xor_sync(0xFFFFFFFFu, sum, off);

    __shared__ float wsum[8];
    int lane = threadIdx.x & 31, wid = threadIdx.x >> 5;
    if (lane == 0) wsum[wid] = sum;
    __syncthreads();
    if (threadIdx.x == 0) {
        float tot = 0.f;
#pragma unroll
        for (int w = 0; w < 8; w++) tot += wsum[w];
        int s = (idx / E_DIM) % S_LEN;
        int e = idx % E_DIM;
        g_buf[idx] = tot * (1.0f / HW) + tpos[s * E_DIM + e];
    }
}

// -------------------------------------------------------------------------
// Kernel 2: per-batch MHA on g[b]  (tiny: 6 tokens x 256 dims)
// One block per batch, 256 threads, all in shared memory.
// -------------------------------------------------------------------------
__global__ void __launch_bounds__(256) attn_kernel(
    const float* __restrict__ Wq, const float* __restrict__ bq,
    const float* __restrict__ Wk, const float* __restrict__ bk,
    const float* __restrict__ Wv, const float* __restrict__ bv,
    const float* __restrict__ Wo, const float* __restrict__ bo,
    float* __restrict__ attn_out, int write_attn)
{
    int b = blockIdx.x;
    int tid = threadIdx.x;

    __shared__ float sg[S_LEN][E_DIM];
    __shared__ float sq[S_LEN][E_DIM];
    __shared__ float sk[S_LEN][E_DIM];
    __shared__ float sv[S_LEN][E_DIM];
    __shared__ float sat[S_LEN][E_DIM];
    __shared__ float sc[NH][S_LEN][S_LEN];

    // load g[b]
    for (int i = tid; i < S_LEN * E_DIM; i += 256)
        sg[i / E_DIM][i % E_DIM] = g_buf[b * S_LEN * E_DIM + i];
    __syncthreads();

    // QKV projections: q[s][e] = g[s] . Wq_row[e] + bq[e]   (Wq rows contiguous)
    for (int i = tid; i < S_LEN * E_DIM; i += 256) {
        int s = i / E_DIM, e = i % E_DIM;
        const float4* wq = reinterpret_cast<const float4*>(Wq + e * E_DIM);
        const float4* wk = reinterpret_cast<const float4*>(Wk + e * E_DIM);
        const float4* wv = reinterpret_cast<const float4*>(Wv + e * E_DIM);
        const float4* gv = reinterpret_cast<const float4*>(&sg[s][0]);
        float aq = bq[e], ak = bk[e], av = bv[e];
#pragma unroll 4
        for (int j = 0; j < E_DIM / 4; j++) {
            float4 g4 = gv[j];
            float4 q4 = wq[j], k4 = wk[j], v4 = wv[j];
            aq += g4.x * q4.x + g4.y * q4.y + g4.z * q4.z + g4.w * q4.w;
            ak += g4.x * k4.x + g4.y * k4.y + g4.z * k4.z + g4.w * k4.w;
            av += g4.x * v4.x + g4.y * v4.y + g4.z * v4.z + g4.w * v4.w;
        }
        sq[s][e] = aq; sk[s][e] = ak; sv[s][e] = av;
    }
    __syncthreads();

    // causal softmax per (h,s) row: 48 rows, one thread each
    if (tid < NH * S_LEN) {
        int h = tid / S_LEN, s = tid % S_LEN;
        float row[S_LEN];
        const float scale = 0.17677669529663687f;  // 1/sqrt(32)
        float mx = -1e30f;
        for (int t = 0; t <= s; t++) {
            float d = 0.f;
#pragma unroll
            for (int j = 0; j < HD; j++)
                d += sq[s][h * HD + j] * sk[t][h * HD + j];
            d *= scale;
            row[t] = d;
            mx = fmaxf(mx, d);
        }
        float den = 0.f;
        for (int t = 0; t <= s; t++) { row[t] = __expf(row[t] - mx); den += row[t]; }
        float inv = 1.f / den;
#pragma unroll
        for (int t = 0; t < S_LEN; t++)
            sc[h][s][t] = (t <= s) ? row[t] * inv : 0.f;
    }
    __syncthreads();

    // write attn [b,h,s,t] (sc is contiguous in exactly that order)
    if (write_attn) {
        const float* scp = &sc[0][0][0];
        for (int i = tid; i < NH * S_LEN * S_LEN; i += 256)
            attn_out[b * NH * S_LEN * S_LEN + i] = scp[i];
    }

    // attended[s][e] = sum_t attn[h][s][t] * v[t][e],  h = e / HD
    for (int i = tid; i < S_LEN * E_DIM; i += 256) {
        int s = i / E_DIM, e = i % E_DIM;
        int h = e / HD;
        float a = 0.f;
        for (int t = 0; t <= s; t++)
            a += sc[h][s][t] * sv[t][e];
        sat[s][e] = a;
    }
    __syncthreads();

    // out_g[s][e] = attended[s] . Wo_row[e] + bo[e]
    for (int i = tid; i < S_LEN * E_DIM; i += 256) {
        int s = i / E_DIM, e = i % E_DIM;
        const float4* wo = reinterpret_cast<const float4*>(Wo + e * E_DIM);
        const float4* av = reinterpret_cast<const float4*>(&sat[s][0]);
        float a = bo[e];
#pragma unroll 4
        for (int j = 0; j < E_DIM / 4; j++) {
            float4 a4 = av[j];
            float4 w4 = wo[j];
            a += a4.x * w4.x + a4.y * w4.y + a4.z * w4.z + a4.w * w4.w;
        }
        og_buf[b * S_LEN * E_DIM + i] = a;
    }
}

// -------------------------------------------------------------------------
// Kernel 3: cross[b,s,e,h,w] = ff[b,s,e,h,w] + out_g[b,s,e]
// One block per (b,s,e) slice; pure streaming float4.
// -------------------------------------------------------------------------
__global__ void __launch_bounds__(256) add_kernel(
    const float* __restrict__ ff, float* __restrict__ out, int total)
{
    int idx = blockIdx.x;
    if (idx >= total) return;
    float add = og_buf[idx];
    const float4* p = reinterpret_cast<const float4*>(ff + (size_t)idx * HW);
    float4* o = reinterpret_cast<float4*>(out + (size_t)idx * HW);
#pragma unroll
    for (int i = 0; i < 4; i++) {
        float4 v = p[threadIdx.x + i * 256];
        v.x += add; v.y += add; v.z += add; v.w += add;
        o[threadIdx.x + i * 256] = v;
    }
}

extern "C" void kernel_launch(void* const* d_in, const int* in_sizes, int n_in,
                              void* d_out, int out_size)
{
    const float* ff   = (const float*)d_in[0];
    const float* Wq   = (const float*)d_in[1];
    const float* bq   = (const float*)d_in[2];
    const float* Wk   = (const float*)d_in[3];
    const float* bk   = (const float*)d_in[4];
    const float* Wv   = (const float*)d_in[5];
    const float* bv   = (const float*)d_in[6];
    const float* Wo   = (const float*)d_in[7];
    const float* bo   = (const float*)d_in[8];
    const float* tpos = (const float*)d_in[9];

    int ff_elems = in_sizes[0];                       // B*S*E*H*W
    int B = ff_elems / (S_LEN * E_DIM * HW);          // 16
    int slices = B * S_LEN * E_DIM;                   // 24576

    float* cross = (float*)d_out;
    int attn_elems = B * NH * S_LEN * S_LEN;          // 4608
    int write_attn = (out_size >= ff_elems + attn_elems) ? 1 : 0;
    float* attn_out = cross + ff_elems;

    pool_kernel<<<slices, 256>>>(ff, tpos, slices);
    attn_kernel<<<B, 256>>>(Wq, bq, Wk, bk, Wv, bv, Wo, bo, attn_out, write_attn);
    add_kernel<<<slices, 256>>>(ff, cross, slices);
}

// round 3
// speedup vs baseline: 1.6342x; 1.6342x over previous
#include <cuda_runtime.h>
#include <cuda_bf16.h>

#define S_LEN 6
#define E_DIM 256
#define NH    8
#define HD    32
#define HW    4096   // 64*64
#define B_MAX 16
#define BSE   (B_MAX * S_LEN * E_DIM)

// Scratch (no cudaMalloc allowed)
__device__ float g_buf[BSE];          // pooled + pos
__device__ float q_buf[BSE];
__device__ float k_buf[BSE];
__device__ float v_buf[BSE];
__device__ float at_buf[BSE];         // attended (pre-Wo)
__device__ float og_buf[BSE];         // out projection

// -------------------------------------------------------------------------
// Kernel 1: global spatial mean over 64x64 + temporal_pos  -> g[b,s,e]
// -------------------------------------------------------------------------
__global__ void __launch_bounds__(256) pool_kernel(
    const float* __restrict__ ff, const float* __restrict__ tpos, int total)
{
    int idx = blockIdx.x;                 // b*S*E + s*E + e
    if (idx >= total) return;
    const float4* p = reinterpret_cast<const float4*>(ff + (size_t)idx * HW);

    float sum = 0.f;
#pragma unroll
    for (int i = 0; i < 4; i++) {
        float4 v = __ldcs(&p[threadIdx.x + i * 256]);
        sum += (v.x + v.y) + (v.z + v.w);
    }
#pragma unroll
    for (int off = 16; off > 0; off >>= 1)
        sum += __shfl_xor_sync(0xFFFFFFFFu, sum, off);

    __shared__ float wsum[8];
    int lane = threadIdx.x & 31, wid = threadIdx.x >> 5;
    if (lane == 0) wsum[wid] = sum;
    __syncthreads();
    if (threadIdx.x == 0) {
        float tot = 0.f;
#pragma unroll
        for (int w = 0; w < 8; w++) tot += wsum[w];
        int s = (idx / E_DIM) % S_LEN;
        int e = idx % E_DIM;
        g_buf[idx] = tot * (1.0f / HW) + tpos[s * E_DIM + e];
    }
}

// -------------------------------------------------------------------------
// Kernel 2: QKV projections. One block per (b,s); warp-cooperative dots.
// Lanes stride j -> coalesced 512B weight loads.
// -------------------------------------------------------------------------
__global__ void __launch_bounds__(256) qkv_kernel(
    const float* __restrict__ Wq, const float* __restrict__ bq,
    const float* __restrict__ Wk, const float* __restrict__ bk,
    const float* __restrict__ Wv, const float* __restrict__ bv)
{
    int bs = blockIdx.x;                  // b*S_LEN + s
    int tid = threadIdx.x;
    __shared__ float sg[E_DIM];
    sg[tid] = g_buf[bs * E_DIM + tid];
    __syncthreads();

    int warp = tid >> 5, lane = tid & 31;
    const float4* grow = reinterpret_cast<const float4*>(sg);

    for (int d = warp; d < 3 * E_DIM; d += 8) {
        int which = d >> 8;               // 0=q 1=k 2=v
        int e = d & 255;
        const float* W = (which == 0) ? Wq : (which == 1) ? Wk : Wv;
        const float* bias = (which == 0) ? bq : (which == 1) ? bk : bv;
        const float4* wrow = reinterpret_cast<const float4*>(W + e * E_DIM);
        float acc = 0.f;
#pragma unroll
        for (int i = 0; i < 2; i++) {
            float4 w4 = wrow[lane + 32 * i];
            float4 g4 = grow[lane + 32 * i];
            acc += w4.x * g4.x + w4.y * g4.y + w4.z * g4.z + w4.w * g4.w;
        }
#pragma unroll
        for (int off = 16; off > 0; off >>= 1)
            acc += __shfl_xor_sync(0xFFFFFFFFu, acc, off);
        if (lane == 0) {
            float r = acc + bias[e];
            float* dst = (which == 0) ? q_buf : (which == 1) ? k_buf : v_buf;
            dst[bs * E_DIM + e] = r;
        }
    }
}

// -------------------------------------------------------------------------
// Kernel 3: per-batch causal softmax + AV. One block per batch. All smem.
// -------------------------------------------------------------------------
__global__ void __launch_bounds__(256) attn_core_kernel(
    float* __restrict__ attn_out, int write_attn)
{
    int b = blockIdx.x;
    int tid = threadIdx.x;

    __shared__ float sq[S_LEN][E_DIM];
    __shared__ float sk[S_LEN][E_DIM];
    __shared__ float sv[S_LEN][E_DIM];
    __shared__ float sc[NH][S_LEN][S_LEN];

    for (int i = tid; i < S_LEN * E_DIM; i += 256) {
        sq[i / E_DIM][i % E_DIM] = q_buf[b * S_LEN * E_DIM + i];
        sk[i / E_DIM][i % E_DIM] = k_buf[b * S_LEN * E_DIM + i];
        sv[i / E_DIM][i % E_DIM] = v_buf[b * S_LEN * E_DIM + i];
    }
    __syncthreads();

    if (tid < NH * S_LEN) {
        int h = tid / S_LEN, s = tid % S_LEN;
        float row[S_LEN];
        const float scale = 0.17677669529663687f;  // 1/sqrt(32)
        float mx = -1e30f;
        for (int t = 0; t <= s; t++) {
            float d = 0.f;
#pragma unroll
            for (int j = 0; j < HD; j++)
                d += sq[s][h * HD + j] * sk[t][h * HD + j];
            d *= scale;
            row[t] = d;
            mx = fmaxf(mx, d);
        }
        float den = 0.f;
        for (int t = 0; t <= s; t++) { row[t] = __expf(row[t] - mx); den += row[t]; }
        float inv = 1.f / den;
#pragma unroll
        for (int t = 0; t < S_LEN; t++)
            sc[h][s][t] = (t <= s) ? row[t] * inv : 0.f;
    }
    __syncthreads();

    if (write_attn) {
        const float* scp = &sc[0][0][0];
        for (int i = tid; i < NH * S_LEN * S_LEN; i += 256)
            attn_out[b * NH * S_LEN * S_LEN + i] = scp[i];
    }

    // attended[s][e] = sum_t sc[h][s][t] * v[t][e],  h = e / HD
    for (int i = tid; i < S_LEN * E_DIM; i += 256) {
        int s = i / E_DIM, e = i % E_DIM;
        int h = e / HD;
        float a = 0.f;
        for (int t = 0; t <= s; t++)
            a += sc[h][s][t] * sv[t][e];
        at_buf[b * S_LEN * E_DIM + i] = a;
    }
}

// -------------------------------------------------------------------------
// Kernel 4: output projection. One block per (b,s); warp-cooperative dots.
// -------------------------------------------------------------------------
__global__ void __launch_bounds__(256) oproj_kernel(
    const float* __restrict__ Wo, const float* __restrict__ bo)
{
    int bs = blockIdx.x;
    int tid = threadIdx.x;
    __shared__ float sa[E_DIM];
    sa[tid] = at_buf[bs * E_DIM + tid];
    __syncthreads();

    int warp = tid >> 5, lane = tid & 31;
    const float4* arow = reinterpret_cast<const float4*>(sa);

    for (int e = warp; e < E_DIM; e += 8) {
        const float4* wrow = reinterpret_cast<const float4*>(Wo + e * E_DIM);
        float acc = 0.f;
#pragma unroll
        for (int i = 0; i < 2; i++) {
            float4 w4 = wrow[lane + 32 * i];
            float4 a4 = arow[lane + 32 * i];
            acc += w4.x * a4.x + w4.y * a4.y + w4.z * a4.z + w4.w * a4.w;
        }
#pragma unroll
        for (int off = 16; off > 0; off >>= 1)
            acc += __shfl_xor_sync(0xFFFFFFFFu, acc, off);
        if (lane == 0)
            og_buf[bs * E_DIM + e] = acc + bo[e];
    }
}

// -------------------------------------------------------------------------
// Kernel 5: cross[b,s,e,h,w] = ff[b,s,e,h,w] + out_g[b,s,e]
// -------------------------------------------------------------------------
__global__ void __launch_bounds__(256) add_kernel(
    const float* __restrict__ ff, float* __restrict__ out, int total)
{
    int idx = blockIdx.x;
    if (idx >= total) return;
    float add = og_buf[idx];
    const float4* p = reinterpret_cast<const float4*>(ff + (size_t)idx * HW);
    float4* o = reinterpret_cast<float4*>(out + (size_t)idx * HW);
#pragma unroll
    for (int i = 0; i < 4; i++) {
        float4 v = __ldcs(&p[threadIdx.x + i * 256]);
        v.x += add; v.y += add; v.z += add; v.w += add;
        __stcs(&o[threadIdx.x + i * 256], v);
    }
}

extern "C" void kernel_launch(void* const* d_in, const int* in_sizes, int n_in,
                              void* d_out, int out_size)
{
    const float* ff   = (const float*)d_in[0];
    const float* Wq   = (const float*)d_in[1];
    const float* bq   = (const float*)d_in[2];
    const float* Wk   = (const float*)d_in[3];
    const float* bk   = (const float*)d_in[4];
    const float* Wv   = (const float*)d_in[5];
    const float* bv   = (const float*)d_in[6];
    const float* Wo   = (const float*)d_in[7];
    const float* bo   = (const float*)d_in[8];
    const float* tpos = (const float*)d_in[9];

    int ff_elems = in_sizes[0];                       // B*S*E*H*W
    int B = ff_elems / (S_LEN * E_DIM * HW);          // 16
    int slices = B * S_LEN * E_DIM;                   // 24576

    float* cross = (float*)d_out;
    int attn_elems = B * NH * S_LEN * S_LEN;          // 4608
    int write_attn = (out_size >= ff_elems + attn_elems) ? 1 : 0;
    float* attn_out = cross + ff_elems;

    pool_kernel<<<slices, 256>>>(ff, tpos, slices);
    qkv_kernel<<<B * S_LEN, 256>>>(Wq, bq, Wk, bk, Wv, bv);
    attn_core_kernel<<<B, 256>>>(attn_out, write_attn);
    oproj_kernel<<<B * S_LEN, 256>>>(Wo, bo);
    add_kernel<<<slices, 256>>>(ff, cross, slices);
}